// round 1
// baseline (speedup 1.0000x reference)
#include <cuda_runtime.h>
#include <cuda_bf16.h>
#include <math.h>

// Problem constants
#define BATCH 16
#define LSEQ  2048
#define DIM   512
#define CDIST 21      // 2*10 + 1
#define CLIPD 10

// GEMM tiling
#define TM 128
#define TN 128
#define BK 8
#define NTILE (LSEQ / TM)          // 16 tiles per dim
#define NPAIRS (NTILE * (NTILE + 1) / 2)   // 136 triangular tile pairs

// Scratch: kp[b, i, c] = sum_d key[b,i,d] * params[c,d]
__device__ float g_kp[BATCH * LSEQ * CDIST];
__device__ int   g_mask_i32;

// ---------------------------------------------------------------------------
// Packed fp32x2 helpers (sm_103a FFMA2 — only reachable via PTX)
// ---------------------------------------------------------------------------
__device__ __forceinline__ void pack2(unsigned long long& o, float lo, float hi) {
    asm("mov.b64 %0, {%1, %2};" : "=l"(o) : "f"(lo), "f"(hi));
}
__device__ __forceinline__ void fma2(unsigned long long& acc, unsigned long long a,
                                     unsigned long long b) {
    asm("fma.rn.f32x2 %0, %1, %2, %0;" : "+l"(acc) : "l"(a), "l"(b));
}
__device__ __forceinline__ float2 unpack2(unsigned long long u) {
    float2 f;
    asm("mov.b64 {%0, %1}, %2;" : "=f"(f.x), "=f"(f.y) : "l"(u));
    return f;
}

// ---------------------------------------------------------------------------
// Mask dtype detector: numpy bool (1B) vs int32 (4B). Values are 0/1, so for
// int32 every byte at offset 4i+{1,2,3} is zero; for bool those offsets are
// random 0/1 bytes. Deterministic on fixed inputs.
// ---------------------------------------------------------------------------
__global__ void detect_mask_kernel(const unsigned char* m) {
    int i32 = 1;
    for (int i = 0; i < 256; ++i) {
        if (m[i * 4 + 1] | m[i * 4 + 2] | m[i * 4 + 3]) { i32 = 0; break; }
    }
    g_mask_i32 = i32;
}

__device__ __forceinline__ bool is_masked(const void* mask, int idx, int m_i32) {
    if (m_i32) return ((const int*)mask)[idx] != 0;
    return ((const unsigned char*)mask)[idx] != 0;
}

// ---------------------------------------------------------------------------
// Kernel A: kp[b,i,c] = key[b,i,:] . params[c,:]
// One warp per row; params staged in SMEM.
// ---------------------------------------------------------------------------
__global__ __launch_bounds__(256) void compute_kp_kernel(const float* __restrict__ key,
                                                         const float* __restrict__ params) {
    __shared__ float sp[CDIST * DIM];   // 43008 B
    int tid = threadIdx.x;
    for (int i = tid; i < CDIST * DIM; i += 256) sp[i] = params[i];
    __syncthreads();

    int warp = tid >> 5;
    int lane = tid & 31;
    int row = blockIdx.x * 8 + warp;   // 0 .. BATCH*LSEQ-1

    const float* krow = key + (size_t)row * DIM;
    float kr[16];
#pragma unroll
    for (int t = 0; t < 16; ++t) kr[t] = krow[lane + 32 * t];

    float* out = g_kp + (size_t)row * CDIST;
#pragma unroll 1
    for (int c = 0; c < CDIST; ++c) {
        const float* prow = sp + c * DIM;
        float acc = 0.f;
#pragma unroll
        for (int t = 0; t < 16; ++t) acc += kr[t] * prow[lane + 32 * t];
#pragma unroll
        for (int o = 16; o > 0; o >>= 1) acc += __shfl_xor_sync(0xFFFFFFFFu, acc, o);
        if (lane == 0) out[c] = acc;
    }
}

// ---------------------------------------------------------------------------
// Kernel B: triangular symmetric SGEMM  S = K K^T  (128x128x8 tiles, fp32x2),
// epilogue adds relative-position bias + mask for both orientations, writes
// raw scores to out.
// ---------------------------------------------------------------------------
__global__ __launch_bounds__(256, 1) void attn_scores_kernel(const float* __restrict__ key,
                                                             const void* __restrict__ mask,
                                                             float* __restrict__ out) {
    __shared__ float As[2][BK][TM + 4];
    __shared__ float Bs[2][BK][TN + 4];

    // decode triangular pair index -> (bi, bj), bi <= bj
    int t = blockIdx.x;
    int bi = 0;
    while (t >= NTILE - bi) { t -= NTILE - bi; ++bi; }
    int bj = bi + t;
    int b = blockIdx.y;
    int bL = b * LSEQ;

    int i0 = bi * TM;
    int j0 = bj * TN;

    int tid = threadIdx.x;
    int tx = tid & 15;          // 0..15  -> 8 cols each
    int ty = tid >> 4;          // 0..15  -> 8 rows each

    // global load mapping: each thread loads 1 float4 of A-tile and B-tile
    int ldRow = tid >> 1;            // 0..127
    int ldK = (tid & 1) * 4;         // 0 or 4
    const float* aLoad = key + (size_t)(bL + i0 + ldRow) * DIM + ldK;
    const float* bLoad = key + (size_t)(bL + j0 + ldRow) * DIM + ldK;

    unsigned long long acc[8][4];
#pragma unroll
    for (int r = 0; r < 8; ++r)
#pragma unroll
        for (int p = 0; p < 4; ++p) acc[r][p] = 0ull;

    int m_i32 = g_mask_i32;

    // preload first k-tile
    {
        float4 ag = *(const float4*)(aLoad);
        float4 bg = *(const float4*)(bLoad);
        As[0][ldK + 0][ldRow] = ag.x; As[0][ldK + 1][ldRow] = ag.y;
        As[0][ldK + 2][ldRow] = ag.z; As[0][ldK + 3][ldRow] = ag.w;
        Bs[0][ldK + 0][ldRow] = bg.x; Bs[0][ldK + 1][ldRow] = bg.y;
        Bs[0][ldK + 2][ldRow] = bg.z; Bs[0][ldK + 3][ldRow] = bg.w;
    }
    __syncthreads();

    int buf = 0;
    const int KT = DIM / BK;   // 64
#pragma unroll 1
    for (int kt = 0; kt < KT; ++kt) {
        float4 ag, bg;
        if (kt < KT - 1) {
            ag = *(const float4*)(aLoad + (kt + 1) * BK);
            bg = *(const float4*)(bLoad + (kt + 1) * BK);
        }
#pragma unroll
        for (int k = 0; k < BK; ++k) {
            const float* arow = &As[buf][k][ty * 8];
            const float* brow = &Bs[buf][k][tx * 8];
            float4 a0 = *(const float4*)arow;
            float4 a1 = *(const float4*)(arow + 4);
            float4 b0 = *(const float4*)brow;
            float4 b1 = *(const float4*)(brow + 4);
            unsigned long long bp0, bp1, bp2, bp3;
            pack2(bp0, b0.x, b0.y); pack2(bp1, b0.z, b0.w);
            pack2(bp2, b1.x, b1.y); pack2(bp3, b1.z, b1.w);
            float ar[8] = {a0.x, a0.y, a0.z, a0.w, a1.x, a1.y, a1.z, a1.w};
#pragma unroll
            for (int r = 0; r < 8; ++r) {
                unsigned long long ap;
                pack2(ap, ar[r], ar[r]);
                fma2(acc[r][0], ap, bp0);
                fma2(acc[r][1], ap, bp1);
                fma2(acc[r][2], ap, bp2);
                fma2(acc[r][3], ap, bp3);
            }
        }
        if (kt < KT - 1) {
            int nb = buf ^ 1;
            As[nb][ldK + 0][ldRow] = ag.x; As[nb][ldK + 1][ldRow] = ag.y;
            As[nb][ldK + 2][ldRow] = ag.z; As[nb][ldK + 3][ldRow] = ag.w;
            Bs[nb][ldK + 0][ldRow] = bg.x; Bs[nb][ldK + 1][ldRow] = bg.y;
            Bs[nb][ldK + 2][ldRow] = bg.z; Bs[nb][ldK + 3][ldRow] = bg.w;
            __syncthreads();
        }
        buf ^= 1;
    }

    // unpack accumulators
    float accf[8][8];
#pragma unroll
    for (int r = 0; r < 8; ++r)
#pragma unroll
        for (int p = 0; p < 4; ++p) {
            float2 v = unpack2(acc[r][p]);
            accf[r][2 * p] = v.x;
            accf[r][2 * p + 1] = v.y;
        }

    int irBase = i0 + ty * 8;
    int jcBase = j0 + tx * 8;

    // ---- normal orientation: rows i, cols j ----
    bool mj[8];
#pragma unroll
    for (int c = 0; c < 8; ++c) mj[c] = is_masked(mask, bL + jcBase + c, m_i32);

#pragma unroll
    for (int r = 0; r < 8; ++r) {
        int ir = irBase + r;
        const float* kpRow = g_kp + (size_t)(bL + ir) * CDIST;
        float rv[8];
#pragma unroll
        for (int c = 0; c < 8; ++c) {
            int dd = (jcBase + c) - ir;
            dd = min(CLIPD, max(-CLIPD, dd)) + CLIPD;
            float v = accf[r][c] + __ldg(kpRow + dd);
            rv[c] = mj[c] ? -1e20f : v;
        }
        float* op = out + ((size_t)(bL + ir)) * LSEQ + jcBase;
        *(float4*)op = make_float4(rv[0], rv[1], rv[2], rv[3]);
        *(float4*)(op + 4) = make_float4(rv[4], rv[5], rv[6], rv[7]);
    }

    // ---- mirrored orientation: rows j, cols i (skip diagonal tiles) ----
    if (bi != bj) {
        bool mi[8];
#pragma unroll
        for (int r = 0; r < 8; ++r) mi[r] = is_masked(mask, bL + irBase + r, m_i32);

#pragma unroll
        for (int c = 0; c < 8; ++c) {
            int jr = jcBase + c;
            const float* kpRow = g_kp + (size_t)(bL + jr) * CDIST;
            float rv[8];
#pragma unroll
            for (int r = 0; r < 8; ++r) {
                int dd = (irBase + r) - jr;
                dd = min(CLIPD, max(-CLIPD, dd)) + CLIPD;
                float v = accf[r][c] + __ldg(kpRow + dd);
                rv[r] = mi[r] ? -1e20f : v;
            }
            float* op = out + ((size_t)(bL + jr)) * LSEQ + irBase;
            *(float4*)op = make_float4(rv[0], rv[1], rv[2], rv[3]);
            *(float4*)(op + 4) = make_float4(rv[4], rv[5], rv[6], rv[7]);
        }
    }
}

// ---------------------------------------------------------------------------
// Kernel C: in-place row softmax over last axis (2048). One block per row.
// ---------------------------------------------------------------------------
__global__ __launch_bounds__(256) void softmax_rows_kernel(float* __restrict__ out) {
    __shared__ float red[8];
    int t = threadIdx.x;
    float* p = out + (size_t)blockIdx.x * LSEQ + t * 8;
    float4 v0 = *(const float4*)p;
    float4 v1 = *(const float4*)(p + 4);
    float v[8] = {v0.x, v0.y, v0.z, v0.w, v1.x, v1.y, v1.z, v1.w};

    float m = v[0];
#pragma unroll
    for (int i = 1; i < 8; ++i) m = fmaxf(m, v[i]);
#pragma unroll
    for (int o = 16; o > 0; o >>= 1) m = fmaxf(m, __shfl_xor_sync(0xFFFFFFFFu, m, o));
    if ((t & 31) == 0) red[t >> 5] = m;
    __syncthreads();
    float mm = red[0];
#pragma unroll
    for (int i = 1; i < 8; ++i) mm = fmaxf(mm, red[i]);
    __syncthreads();

    float e[8];
    float s = 0.f;
#pragma unroll
    for (int i = 0; i < 8; ++i) { e[i] = expf(v[i] - mm); s += e[i]; }
#pragma unroll
    for (int o = 16; o > 0; o >>= 1) s += __shfl_xor_sync(0xFFFFFFFFu, s, o);
    if ((t & 31) == 0) red[t >> 5] = s;
    __syncthreads();
    float tot = 0.f;
#pragma unroll
    for (int i = 0; i < 8; ++i) tot += red[i];
    float inv = 1.0f / tot;

    *(float4*)p = make_float4(e[0] * inv, e[1] * inv, e[2] * inv, e[3] * inv);
    *(float4*)(p + 4) = make_float4(e[4] * inv, e[5] * inv, e[6] * inv, e[7] * inv);
}

// ---------------------------------------------------------------------------
extern "C" void kernel_launch(void* const* d_in, const int* in_sizes, int n_in,
                              void* d_out, int out_size) {
    const float* key = (const float*)d_in[0];
    const void* mask = d_in[1];
    const float* params = (const float*)d_in[2];
    float* out = (float*)d_out;

    detect_mask_kernel<<<1, 1>>>((const unsigned char*)mask);
    compute_kp_kernel<<<BATCH * LSEQ / 8, 256>>>(key, params);
    attn_scores_kernel<<<dim3(NPAIRS, BATCH), 256>>>(key, mask, out);
    softmax_rows_kernel<<<BATCH * LSEQ, 256>>>(out);
}